// round 7
// baseline (speedup 1.0000x reference)
#include <cuda_runtime.h>
#include <math_constants.h>

// x [B=64, C=512, H=28, W=28] fp32; cc [B,28,28] bool widened to int32.
// out [B, 2C]: out[b,c]   = (sum_hw x[b,c,hw]*cc[b,hw] + x[b,c,0]) / max(cnt_b,1)
//              out[b,C+c] = max_hw x[b,c,hw]
//
// Persistent: grid = 148*8 CTAs, each loops grid-stride over 4096 row-groups
// (8 rows each, warp-per-row). Double-buffered smem mask -> ONE barrier per
// iteration. __launch_bounds__(256,8) forces <=32 regs -> 8 CTAs/SM.

#define HW   784
#define HW4  196
#define C_DIM 512
#define THREADS 256
#define ROWS_PER_CTA 8
#define N_GROUPS 4096            // 64*512/8
#define GRID 1184                // 148 SMs * 8 CTAs

__global__ __launch_bounds__(THREADS, 8) void pool_kernel(
    const float* __restrict__ x,
    const int* __restrict__ cc,
    float* __restrict__ out)
{
    __shared__ float s_m[2][HW];   // double-buffered float mask

    const int tid  = threadIdx.x;
    const int wid  = tid >> 5;
    const int lane = tid & 31;

    int buf = 0;
    for (int g = blockIdx.x; g < N_GROUPS; g += GRID, buf ^= 1) {
        const int b  = g >> 6;                 // 64 groups per batch
        const int bc = g * ROWS_PER_CTA + wid; // this warp's row

        const float4* __restrict__ xr =
            reinterpret_cast<const float4*>(x + (size_t)bc * HW);

        // ---- 1. Issue x loads (196 = 6*32 + 4) ----
        float4 v[7];
        #pragma unroll
        for (int j = 0; j < 6; j++) v[j] = xr[lane + 32 * j];
        const bool tail = (lane < 4);
        if (tail) v[6] = xr[lane + 192];

        // ---- 2. Mask -> smem float (overlaps x-load latency) ----
        if (tid < HW4) {
            int4 m = reinterpret_cast<const int4*>(cc + (size_t)b * HW)[tid];
            float4 f;
            f.x = m.x ? 1.0f : 0.0f;
            f.y = m.y ? 1.0f : 0.0f;
            f.z = m.z ? 1.0f : 0.0f;
            f.w = m.w ? 1.0f : 0.0f;
            *reinterpret_cast<float4*>(&s_m[buf][4 * tid]) = f;
        }
        __syncthreads();   // single barrier/iter; double buffer protects reuse

        // ---- 3. Consume: FMA with mask, count, max ----
        const float4* __restrict__ mm =
            reinterpret_cast<const float4*>(s_m[buf]);
        float sum0 = 0.0f, sum1 = 0.0f;
        float cnt  = 0.0f;
        float mx   = -CUDART_INF_F;

        #pragma unroll
        for (int j = 0; j < 6; j++) {
            float4 f = mm[lane + 32 * j];
            sum0 = fmaf(v[j].x, f.x, fmaf(v[j].y, f.y, sum0));
            sum1 = fmaf(v[j].z, f.z, fmaf(v[j].w, f.w, sum1));
            cnt += (f.x + f.y) + (f.z + f.w);
            mx = fmaxf(mx, fmaxf(fmaxf(v[j].x, v[j].y), fmaxf(v[j].z, v[j].w)));
        }
        if (tail) {
            float4 f = mm[lane + 192];
            sum0 = fmaf(v[6].x, f.x, fmaf(v[6].y, f.y, sum0));
            sum1 = fmaf(v[6].z, f.z, fmaf(v[6].w, f.w, sum1));
            cnt += (f.x + f.y) + (f.z + f.w);
            mx = fmaxf(mx, fmaxf(fmaxf(v[6].x, v[6].y), fmaxf(v[6].z, v[6].w)));
        }

        float sum = sum0 + sum1;
        #pragma unroll
        for (int off = 16; off > 0; off >>= 1) {
            sum += __shfl_down_sync(0xffffffffu, sum, off);
            cnt += __shfl_down_sync(0xffffffffu, cnt, off);
            mx   = fmaxf(mx, __shfl_down_sync(0xffffffffu, mx, off));
        }

        if (lane == 0) {
            const int c = bc & (C_DIM - 1);
            sum += v[0].x;                   // + x[b,c,0,0] quirk: already in regs
            float denom = (cnt == 0.0f) ? 1.0f : cnt;
            out[(size_t)b * (2 * C_DIM) + c]         = sum / denom;
            out[(size_t)b * (2 * C_DIM) + C_DIM + c] = mx;
        }
    }
}

extern "C" void kernel_launch(void* const* d_in, const int* in_sizes, int n_in,
                              void* d_out, int out_size)
{
    const float* x  = (const float*)d_in[0];
    const int*   cc = (const int*)d_in[1];
    float*       o  = (float*)d_out;

    pool_kernel<<<GRID, THREADS>>>(x, cc, o);
}

// round 8
// speedup vs baseline: 1.1064x; 1.1064x over previous
#include <cuda_runtime.h>
#include <math_constants.h>

// x [B=64, C=512, H=28, W=28] fp32; cc [B,28,28] bool widened to int32.
// out [B, 2C]: out[b,c]   = (sum_hw x[b,c,hw]*cc[b,hw] + x[b,c,0]) / max(cnt_b,1)
//              out[b,C+c] = max_hw x[b,c,hw]
//
// Warp-per-row, NO smem, NO barrier: each warp streams its 784-float row as
// 7 float4 LDGs (front-batched, MLP=7 -> DRAM) and reads the batch mask as
// 7 int4 LDGs (L1/L2-resident: 3136B/batch reused by 512 warps). Warps are
// fully independent -> no coupling stalls. Grid 4096 x 256 thr.

#define HW   784
#define C_DIM 512
#define THREADS 256
#define ROWS_PER_CTA 8

__global__ __launch_bounds__(THREADS) void pool_kernel(
    const float* __restrict__ x,
    const int* __restrict__ cc,
    float* __restrict__ out)
{
    const int tid  = threadIdx.x;
    const int wid  = tid >> 5;
    const int lane = tid & 31;

    const int bc = blockIdx.x * ROWS_PER_CTA + wid;   // this warp's row
    const int b  = bc >> 9;

    const float4* __restrict__ xr = reinterpret_cast<const float4*>(x + (size_t)bc * HW);
    const int4*   __restrict__ mr = reinterpret_cast<const int4*>(cc + (size_t)b * HW);

    // ---- 1. Front-batch all x loads (196 = 6*32 + 4) ----
    float4 v[7];
    #pragma unroll
    for (int j = 0; j < 6; j++) v[j] = xr[lane + 32 * j];
    const bool tail = (lane < 4);
    if (tail) v[6] = xr[lane + 192];

    // ---- 2. Consume with per-warp mask loads (L1 hits, overlap x latency) ----
    float sum0 = 0.0f, sum1 = 0.0f;
    int   icnt = 0;
    float mx   = -CUDART_INF_F;

    #pragma unroll
    for (int j = 0; j < 6; j++) {
        int4 m = mr[lane + 32 * j];
        sum0 += (m.x ? v[j].x : 0.0f) + (m.y ? v[j].y : 0.0f);
        sum1 += (m.z ? v[j].z : 0.0f) + (m.w ? v[j].w : 0.0f);
        icnt += (m.x != 0) + (m.y != 0) + (m.z != 0) + (m.w != 0);
        mx = fmaxf(mx, fmaxf(fmaxf(v[j].x, v[j].y), fmaxf(v[j].z, v[j].w)));
    }
    if (tail) {
        int4 m = mr[lane + 192];
        sum0 += (m.x ? v[6].x : 0.0f) + (m.y ? v[6].y : 0.0f);
        sum1 += (m.z ? v[6].z : 0.0f) + (m.w ? v[6].w : 0.0f);
        icnt += (m.x != 0) + (m.y != 0) + (m.z != 0) + (m.w != 0);
        mx = fmaxf(mx, fmaxf(fmaxf(v[6].x, v[6].y), fmaxf(v[6].z, v[6].w)));
    }

    // ---- 3. Warp reduce ----
    float sum = sum0 + sum1;
    #pragma unroll
    for (int off = 16; off > 0; off >>= 1) {
        sum  += __shfl_down_sync(0xffffffffu, sum, off);
        icnt += __shfl_down_sync(0xffffffffu, icnt, off);
        mx    = fmaxf(mx, __shfl_down_sync(0xffffffffu, mx, off));
    }

    if (lane == 0) {
        const int c = bc & (C_DIM - 1);
        sum += v[0].x;                       // + x[b,c,0,0] quirk: already in regs
        float fcnt  = (float)icnt;
        float denom = (icnt == 0) ? 1.0f : fcnt;
        out[(size_t)b * (2 * C_DIM) + c]         = sum / denom;
        out[(size_t)b * (2 * C_DIM) + C_DIM + c] = mx;
    }
}

extern "C" void kernel_launch(void* const* d_in, const int* in_sizes, int n_in,
                              void* d_out, int out_size)
{
    const float* x  = (const float*)d_in[0];
    const int*   cc = (const int*)d_in[1];
    float*       o  = (float*)d_out;

    // grid = 32768 rows / 8 rows per CTA
    pool_kernel<<<(64 * C_DIM) / ROWS_PER_CTA, THREADS>>>(x, cc, o);
}